// round 3
// baseline (speedup 1.0000x reference)
#include <cuda_runtime.h>
#include <cstdint>

#define SEQ   2048
#define DMODEL 1024
#define NHEAD 16
#define HDIM  64
#define QKV_STRIDE (3 * DMODEL)

// Scratch (device-global: no runtime allocation allowed)
__device__ float g_qkv[SEQ * 3 * DMODEL];   // [S, 3*DIM]  q|k|v packed
__device__ float g_att[SEQ * DMODEL];       // attention output [S, DIM]

// ---------------------------------------------------------------------------
// SGEMM (NT): C[M,N] = A[M,K] @ B[N,K]^T + bias[N]
// BM=BN=128, BK=8, 256 threads, 8x8 microtile per thread.
// M, N, K all multiples of tile sizes here (2048 x {3072,1024} x 1024).
// ---------------------------------------------------------------------------
__global__ __launch_bounds__(256, 2)
void sgemm_nt(const float* __restrict__ A, const float* __restrict__ B,
              const float* __restrict__ bias, float* __restrict__ C,
              int N, int K) {
    constexpr int BM = 128, BN = 128, BK = 8, PAD = 4;
    __shared__ float As[BK][BM + PAD];
    __shared__ float Bs[BK][BN + PAD];

    const int t  = threadIdx.x;
    const int tx = t & 15;        // 0..15 -> N microtile
    const int ty = t >> 4;        // 0..15 -> M microtile
    const int bm = blockIdx.y * BM;
    const int bn = blockIdx.x * BN;

    // Global-load mapping: 128 rows x 8 k = 1024 floats = 256 float4
    const int lr = t >> 1;            // row within tile (0..127)
    const int lc = (t & 1) * 4;       // k offset (0 or 4)
    const float* Ag = A + (size_t)(bm + lr) * K + lc;
    const float* Bg = B + (size_t)(bn + lr) * K + lc;

    float acc[8][8];
#pragma unroll
    for (int i = 0; i < 8; i++)
#pragma unroll
        for (int j = 0; j < 8; j++) acc[i][j] = 0.f;

    for (int k0 = 0; k0 < K; k0 += BK) {
        float4 a = *(const float4*)(Ag + k0);
        float4 b = *(const float4*)(Bg + k0);
        __syncthreads();
        As[lc + 0][lr] = a.x; As[lc + 1][lr] = a.y;
        As[lc + 2][lr] = a.z; As[lc + 3][lr] = a.w;
        Bs[lc + 0][lr] = b.x; Bs[lc + 1][lr] = b.y;
        Bs[lc + 2][lr] = b.z; Bs[lc + 3][lr] = b.w;
        __syncthreads();

#pragma unroll
        for (int kk = 0; kk < BK; kk++) {
            float ra[8], rb[8];
            *(float4*)(ra)     = *(const float4*)&As[kk][ty * 8];
            *(float4*)(ra + 4) = *(const float4*)&As[kk][ty * 8 + 4];
            *(float4*)(rb)     = *(const float4*)&Bs[kk][tx * 8];
            *(float4*)(rb + 4) = *(const float4*)&Bs[kk][tx * 8 + 4];
#pragma unroll
            for (int i = 0; i < 8; i++)
#pragma unroll
                for (int j = 0; j < 8; j++)
                    acc[i][j] = fmaf(ra[i], rb[j], acc[i][j]);
        }
    }

    float bb[8];
#pragma unroll
    for (int j = 0; j < 8; j++) bb[j] = bias[bn + tx * 8 + j];

#pragma unroll
    for (int i = 0; i < 8; i++) {
        float* Cp = C + (size_t)(bm + ty * 8 + i) * N + bn + tx * 8;
        float4 v0 = make_float4(acc[i][0] + bb[0], acc[i][1] + bb[1],
                                acc[i][2] + bb[2], acc[i][3] + bb[3]);
        float4 v1 = make_float4(acc[i][4] + bb[4], acc[i][5] + bb[5],
                                acc[i][6] + bb[6], acc[i][7] + bb[7]);
        *(float4*)(Cp)     = v0;
        *(float4*)(Cp + 4) = v1;
    }
}

// ---------------------------------------------------------------------------
// RoPE applied in-place to q and k portions of g_qkv.
// rotate_half: out[0:32] = -x[32:64], out[32:64] = x[0:32]; cos/sin duplicated
// across the two halves (cos[s,d] == cos[s,d+32]).
// One thread handles one (stream, s, h, d<32) pair -> writes both halves.
// ---------------------------------------------------------------------------
__global__ __launch_bounds__(256)
void rope_kernel(float* __restrict__ qkv, const float* __restrict__ sinp,
                 const float* __restrict__ cosp) {
    int idx = blockIdx.x * blockDim.x + threadIdx.x;
    // idx = which*(S*H*32) + s*(H*32) + h*32 + d ; total = 2*2048*512 = 2^21
    int d     = idx & 31;
    int h     = (idx >> 5) & (NHEAD - 1);
    int s     = (idx >> 9) & (SEQ - 1);
    int which = idx >> 20;            // 0 = q, 1 = k
    float* base = qkv + (size_t)s * QKV_STRIDE + which * DMODEL + h * HDIM;
    float x1 = base[d];
    float x2 = base[d + 32];
    float cs = cosp[s * HDIM + d];
    float sn = sinp[s * HDIM + d];
    base[d]      = x1 * cs - x2 * sn;   // x1*cos + (-x2)*sin
    base[d + 32] = x2 * cs + x1 * sn;   // x2*cos + ( x1)*sin
}

// ---------------------------------------------------------------------------
// Flash attention (fp32, online softmax).
// Block = (head h, 64-query tile). 256 threads: thread t owns query row
// r = t>>2 and "lane group" c = t&3. c selects 16 interleaved keys
// (j = c + 4*jj) for the score phase and 16 contiguous output dims
// (d = c*16+u) for the PV phase. Q row lives in 64 registers.
// ---------------------------------------------------------------------------
constexpr int KS_STRIDE = 68;   // pad so 4 consecutive rows hit distinct banks
constexpr int VS_STRIDE = 64;
constexpr int PS_STRIDE = 65;
constexpr int SMEM_FLASH =
    (64 * KS_STRIDE + 64 * VS_STRIDE + 64 * PS_STRIDE) * (int)sizeof(float);

__global__ __launch_bounds__(256, 1)
void flash_attn(const float* __restrict__ qkv, float* __restrict__ att) {
    extern __shared__ float sm[];
    float* Ks = sm;
    float* Vs = Ks + 64 * KS_STRIDE;
    float* Ps = Vs + 64 * VS_STRIDE;

    const int h  = blockIdx.y;
    const int q0 = blockIdx.x * 64;
    const int t  = threadIdx.x;
    const int r  = t >> 2;
    const int c  = t & 3;

    // Q row -> registers (4 threads per row read redundantly; L1/L2 absorbs it)
    float qreg[64];
    {
        const float* qp = qkv + (size_t)(q0 + r) * QKV_STRIDE + h * HDIM;
#pragma unroll
        for (int d4 = 0; d4 < 16; d4++) {
            float4 v = *(const float4*)(qp + 4 * d4);
            qreg[4 * d4 + 0] = v.x; qreg[4 * d4 + 1] = v.y;
            qreg[4 * d4 + 2] = v.z; qreg[4 * d4 + 3] = v.w;
        }
    }

    float m_r = -3.0e38f, l_r = 0.f;
    float acc[16];
#pragma unroll
    for (int u = 0; u < 16; u++) acc[u] = 0.f;

    const float* kbase = qkv + DMODEL + h * HDIM;
    const float* vbase = qkv + 2 * DMODEL + h * HDIM;

    for (int kt = 0; kt < SEQ / 64; kt++) {
        const int kk0 = kt * 64;
        __syncthreads();   // prior iteration done with Ks/Vs/Ps
        // Cooperative, fully-coalesced K/V tile load: 1024 float4 / 256 thr
#pragma unroll
        for (int i = 0; i < 4; i++) {
            int li  = i * 256 + t;
            int row = li >> 4;
            int col = (li & 15) * 4;
            const float* kp = kbase + (size_t)(kk0 + row) * QKV_STRIDE + col;
            const float* vp = vbase + (size_t)(kk0 + row) * QKV_STRIDE + col;
            *(float4*)&Ks[row * KS_STRIDE + col] = *(const float4*)kp;
            *(float4*)&Vs[row * VS_STRIDE + col] = *(const float4*)vp;
        }
        __syncthreads();

        // Scores: 16 interleaved keys per thread, float4 K reads
        float sc[16];
#pragma unroll
        for (int jj = 0; jj < 16; jj++) {
            int j = c + 4 * jj;
            const float4* krow = (const float4*)&Ks[j * KS_STRIDE];
            float sv = 0.f;
#pragma unroll
            for (int d4 = 0; d4 < 16; d4++) {
                float4 kv = krow[d4];
                sv = fmaf(qreg[4 * d4 + 0], kv.x, sv);
                sv = fmaf(qreg[4 * d4 + 1], kv.y, sv);
                sv = fmaf(qreg[4 * d4 + 2], kv.z, sv);
                sv = fmaf(qreg[4 * d4 + 3], kv.w, sv);
            }
            sc[jj] = sv * 0.125f;   // 1/sqrt(64)
        }

        // Online softmax: reduce across the 4 lanes sharing this row
        float mt = sc[0];
#pragma unroll
        for (int jj = 1; jj < 16; jj++) mt = fmaxf(mt, sc[jj]);
        mt = fmaxf(mt, __shfl_xor_sync(0xffffffffu, mt, 1));
        mt = fmaxf(mt, __shfl_xor_sync(0xffffffffu, mt, 2));
        float m_new = fmaxf(m_r, mt);
        float alpha = __expf(m_r - m_new);
        float lt = 0.f;
#pragma unroll
        for (int jj = 0; jj < 16; jj++) {
            float p = __expf(sc[jj] - m_new);
            Ps[r * PS_STRIDE + c + 4 * jj] = p;
            lt += p;
        }
        lt += __shfl_xor_sync(0xffffffffu, lt, 1);
        lt += __shfl_xor_sync(0xffffffffu, lt, 2);
        l_r = l_r * alpha + lt;
        m_r = m_new;
#pragma unroll
        for (int u = 0; u < 16; u++) acc[u] *= alpha;
        __syncthreads();   // Ps visible to all 4 lane groups

        // PV: acc[d] += sum_j P[r][j] * V[j][c*16 + d]
#pragma unroll 8
        for (int j = 0; j < 64; j++) {
            float p = Ps[r * PS_STRIDE + j];
            const float4* vrow = (const float4*)&Vs[j * VS_STRIDE + c * 16];
            float4 v0 = vrow[0], v1 = vrow[1], v2 = vrow[2], v3 = vrow[3];
            acc[0]  = fmaf(p, v0.x, acc[0]);  acc[1]  = fmaf(p, v0.y, acc[1]);
            acc[2]  = fmaf(p, v0.z, acc[2]);  acc[3]  = fmaf(p, v0.w, acc[3]);
            acc[4]  = fmaf(p, v1.x, acc[4]);  acc[5]  = fmaf(p, v1.y, acc[5]);
            acc[6]  = fmaf(p, v1.z, acc[6]);  acc[7]  = fmaf(p, v1.w, acc[7]);
            acc[8]  = fmaf(p, v2.x, acc[8]);  acc[9]  = fmaf(p, v2.y, acc[9]);
            acc[10] = fmaf(p, v2.z, acc[10]); acc[11] = fmaf(p, v2.w, acc[11]);
            acc[12] = fmaf(p, v3.x, acc[12]); acc[13] = fmaf(p, v3.y, acc[13]);
            acc[14] = fmaf(p, v3.z, acc[14]); acc[15] = fmaf(p, v3.w, acc[15]);
        }
    }

    float inv = 1.f / l_r;
    float* op = att + (size_t)(q0 + r) * DMODEL + h * HDIM + c * 16;
#pragma unroll
    for (int u4 = 0; u4 < 4; u4++) {
        float4 v = make_float4(acc[4 * u4 + 0] * inv, acc[4 * u4 + 1] * inv,
                               acc[4 * u4 + 2] * inv, acc[4 * u4 + 3] * inv);
        *(float4*)(op + 4 * u4) = v;
    }
}

// ---------------------------------------------------------------------------
extern "C" void kernel_launch(void* const* d_in, const int* in_sizes, int n_in,
                              void* d_out, int out_size) {
    const float* x     = (const float*)d_in[0];
    const float* sinp  = (const float*)d_in[1];
    const float* cosp  = (const float*)d_in[2];
    const float* Wqkv  = (const float*)d_in[3];
    const float* bqkv  = (const float*)d_in[4];
    const float* Wproj = (const float*)d_in[5];
    const float* bproj = (const float*)d_in[6];
    float* out = (float*)d_out;

    float* qkv = nullptr;
    float* att = nullptr;
    cudaGetSymbolAddress((void**)&qkv, g_qkv);
    cudaGetSymbolAddress((void**)&att, g_att);

    // 1) QKV = x @ Wqkv^T + b  (M=2048, N=3072, K=1024)
    {
        dim3 grid(3072 / 128, SEQ / 128);
        sgemm_nt<<<grid, 256>>>(x, Wqkv, bqkv, qkv, 3072, DMODEL);
    }
    // 2) RoPE on q and k (2^21 elements -> 8192 blocks)
    rope_kernel<<<(2 * SEQ * NHEAD * 32) / 256, 256>>>(qkv, sinp, cosp);

    // 3) Flash attention: 32 q-tiles x 16 heads
    cudaFuncSetAttribute(flash_attn, cudaFuncAttributeMaxDynamicSharedMemorySize,
                         SMEM_FLASH);
    {
        dim3 grid(SEQ / 64, NHEAD);
        flash_attn<<<grid, 256, SMEM_FLASH>>>(qkv, att);
    }
    // 4) out = att @ Wproj^T + b  (M=2048, N=1024, K=1024)
    {
        dim3 grid(DMODEL / 128, SEQ / 128);
        sgemm_nt<<<grid, 256>>>(att, Wproj, bproj, out, DMODEL, DMODEL);
    }
}

// round 5
// speedup vs baseline: 2.4457x; 2.4457x over previous
#include <cuda_runtime.h>
#include <cstdint>

#define SEQ    2048
#define DMODEL 1024
#define NHEAD  16
#define HDIM   64
#define QKV_STRIDE (3 * DMODEL)

// Scratch (device-global: no runtime allocation allowed)
__device__ float g_qkv[SEQ * 3 * DMODEL];   // [S, 3*DIM]  q|k|v packed
__device__ float g_att[SEQ * DMODEL];       // attention output [S, DIM]

// ---------------------------------------------------------------------------
// SGEMM (NT): C[M,N] = A[M,K] @ B[N,K]^T + bias[N]
// BM=BN=128, BK=16, 256 threads, 8x8 microtile, register double-buffered
// global loads (prefetch tile k0+16 while computing tile k0).
// ---------------------------------------------------------------------------
__global__ __launch_bounds__(256, 2)
void sgemm_nt(const float* __restrict__ A, const float* __restrict__ B,
              const float* __restrict__ bias, float* __restrict__ C,
              int N, int K) {
    constexpr int BM = 128, BN = 128, BK = 16, PAD = 4;
    __shared__ float As[BK][BM + PAD];
    __shared__ float Bs[BK][BN + PAD];

    const int t  = threadIdx.x;
    const int tx = t & 15;        // N microtile
    const int ty = t >> 4;        // M microtile
    const int bm = blockIdx.y * BM;
    const int bn = blockIdx.x * BN;

    // Global-load mapping: 128 rows x 16 k = 2048 floats = 512 float4
    const int lr = t >> 1;            // row within tile (0..127)
    const int lc = (t & 1) * 8;       // k offset (0 or 8), 2 float4 each
    const float* Ag = A + (size_t)(bm + lr) * K + lc;
    const float* Bg = B + (size_t)(bn + lr) * K + lc;

    float acc[8][8];
#pragma unroll
    for (int i = 0; i < 8; i++)
#pragma unroll
        for (int j = 0; j < 8; j++) acc[i][j] = 0.f;

    // preload tile 0 into registers
    float4 a0 = *(const float4*)(Ag);
    float4 a1 = *(const float4*)(Ag + 4);
    float4 b0 = *(const float4*)(Bg);
    float4 b1 = *(const float4*)(Bg + 4);

    for (int k0 = 0; k0 < K; k0 += BK) {
        As[lc + 0][lr] = a0.x; As[lc + 1][lr] = a0.y;
        As[lc + 2][lr] = a0.z; As[lc + 3][lr] = a0.w;
        As[lc + 4][lr] = a1.x; As[lc + 5][lr] = a1.y;
        As[lc + 6][lr] = a1.z; As[lc + 7][lr] = a1.w;
        Bs[lc + 0][lr] = b0.x; Bs[lc + 1][lr] = b0.y;
        Bs[lc + 2][lr] = b0.z; Bs[lc + 3][lr] = b0.w;
        Bs[lc + 4][lr] = b1.x; Bs[lc + 5][lr] = b1.y;
        Bs[lc + 6][lr] = b1.z; Bs[lc + 7][lr] = b1.w;
        __syncthreads();

        if (k0 + BK < K) {   // prefetch next tile while computing this one
            a0 = *(const float4*)(Ag + k0 + BK);
            a1 = *(const float4*)(Ag + k0 + BK + 4);
            b0 = *(const float4*)(Bg + k0 + BK);
            b1 = *(const float4*)(Bg + k0 + BK + 4);
        }

#pragma unroll
        for (int kk = 0; kk < BK; kk++) {
            float ra[8], rb[8];
            *(float4*)(ra)     = *(const float4*)&As[kk][ty * 8];
            *(float4*)(ra + 4) = *(const float4*)&As[kk][ty * 8 + 4];
            *(float4*)(rb)     = *(const float4*)&Bs[kk][tx * 8];
            *(float4*)(rb + 4) = *(const float4*)&Bs[kk][tx * 8 + 4];
#pragma unroll
            for (int i = 0; i < 8; i++)
#pragma unroll
                for (int j = 0; j < 8; j++)
                    acc[i][j] = fmaf(ra[i], rb[j], acc[i][j]);
        }
        __syncthreads();
    }

    float bb[8];
#pragma unroll
    for (int j = 0; j < 8; j++) bb[j] = bias[bn + tx * 8 + j];

#pragma unroll
    for (int i = 0; i < 8; i++) {
        float* Cp = C + (size_t)(bm + ty * 8 + i) * N + bn + tx * 8;
        float4 v0 = make_float4(acc[i][0] + bb[0], acc[i][1] + bb[1],
                                acc[i][2] + bb[2], acc[i][3] + bb[3]);
        float4 v1 = make_float4(acc[i][4] + bb[4], acc[i][5] + bb[5],
                                acc[i][6] + bb[6], acc[i][7] + bb[7]);
        *(float4*)(Cp)     = v0;
        *(float4*)(Cp + 4) = v1;
    }
}

// ---------------------------------------------------------------------------
// RoPE applied in-place to q and k portions of g_qkv.
// ---------------------------------------------------------------------------
__global__ __launch_bounds__(256)
void rope_kernel(float* __restrict__ qkv, const float* __restrict__ sinp,
                 const float* __restrict__ cosp) {
    int idx = blockIdx.x * blockDim.x + threadIdx.x;
    int d     = idx & 31;
    int h     = (idx >> 5) & (NHEAD - 1);
    int s     = (idx >> 9) & (SEQ - 1);
    int which = idx >> 20;            // 0 = q, 1 = k
    float* base = qkv + (size_t)s * QKV_STRIDE + which * DMODEL + h * HDIM;
    float x1 = base[d];
    float x2 = base[d + 32];
    float cs = cosp[s * HDIM + d];
    float sn = sinp[s * HDIM + d];
    base[d]      = x1 * cs - x2 * sn;
    base[d + 32] = x2 * cs + x1 * sn;
}

// ---------------------------------------------------------------------------
// Flash attention v2 (fp32, online softmax, 2-D register tiling).
// Block = (head h, 128-query tile). 256 threads as 16x16 grid:
//   ty = t>>4 owns 8 query rows (ty*8..),  tx = t&15 owns:
//     - 4 keys (tx*4..) in the score phase  (8q x 4k microtile)
//     - 4 out dims (tx*4..) in the PV phase (8q x 4d microtile)
// Q and K staged d-major in smem -> hot loops are float4 LDS with high reuse:
//   score: 3 LDS.128 per 32 FMA; PV: 3 LDS.128 per 32 FMA (~1.5 B/FMA).
// ---------------------------------------------------------------------------
constexpr int BQ  = 128;
constexpr int BKT = 64;
constexpr int SQ  = BQ + 4;    // 132: stride for Qs / Ps rows
constexpr int SK  = BKT + 4;   // 68:  stride for Ks / Vs rows
constexpr int SMEM_FLASH =
    (HDIM * SQ + HDIM * SK + BKT * SK + BKT * SQ) * (int)sizeof(float); // 100 KB

__global__ __launch_bounds__(256, 2)
void flash_attn(const float* __restrict__ qkv, float* __restrict__ att) {
    extern __shared__ float sm[];
    float* Qs = sm;                     // [HDIM][SQ]   d-major
    float* Ks = Qs + HDIM * SQ;         // [HDIM][SK]   d-major
    float* Vs = Ks + HDIM * SK;         // [BKT][SK]    k-major
    float* Ps = Vs + BKT * SK;          // [BKT][SQ]    k-major (P transposed)

    const int h  = blockIdx.y;
    const int q0 = blockIdx.x * BQ;
    const int t  = threadIdx.x;
    const int tx = t & 15;
    const int ty = t >> 4;

    // ---- load Q tile (once), transposed to d-major --------------------------
    {
        const float* qg = qkv + h * HDIM;
#pragma unroll
        for (int it = 0; it < 8; it++) {
            int li = it * 256 + t;           // 2048 float4 total
            int q  = li >> 4;                // 0..127
            int d4 = li & 15;                // 0..15
            float4 v = *(const float4*)(qg + (size_t)(q0 + q) * QKV_STRIDE + d4 * 4);
            Qs[(d4 * 4 + 0) * SQ + q] = v.x;
            Qs[(d4 * 4 + 1) * SQ + q] = v.y;
            Qs[(d4 * 4 + 2) * SQ + q] = v.z;
            Qs[(d4 * 4 + 3) * SQ + q] = v.w;
        }
    }

    float m_r[8], l_r[8], acc[8][4];
#pragma unroll
    for (int i = 0; i < 8; i++) {
        m_r[i] = -3.0e38f; l_r[i] = 0.f;
#pragma unroll
        for (int d = 0; d < 4; d++) acc[i][d] = 0.f;
    }

    const float* kbase = qkv + DMODEL + h * HDIM;
    const float* vbase = qkv + 2 * DMODEL + h * HDIM;

    for (int kt = 0; kt < SEQ / BKT; kt++) {
        const int kk0 = kt * BKT;
        __syncthreads();   // previous PV done with Ks/Vs
        // ---- load K (transposed, d-major) and V (k-major) tiles ------------
#pragma unroll
        for (int it = 0; it < 4; it++) {
            int li = it * 256 + t;           // 1024 float4 total per tensor
            int k  = li >> 4;                // 0..63
            int d4 = li & 15;
            float4 kv = *(const float4*)(kbase + (size_t)(kk0 + k) * QKV_STRIDE + d4 * 4);
            float4 vv = *(const float4*)(vbase + (size_t)(kk0 + k) * QKV_STRIDE + d4 * 4);
            Ks[(d4 * 4 + 0) * SK + k] = kv.x;
            Ks[(d4 * 4 + 1) * SK + k] = kv.y;
            Ks[(d4 * 4 + 2) * SK + k] = kv.z;
            Ks[(d4 * 4 + 3) * SK + k] = kv.w;
            *(float4*)&Vs[k * SK + d4 * 4] = vv;
        }
        __syncthreads();

        // ---- scores: 8q x 4k microtile -------------------------------------
        float sc[8][4];
#pragma unroll
        for (int i = 0; i < 8; i++)
#pragma unroll
            for (int j = 0; j < 4; j++) sc[i][j] = 0.f;

#pragma unroll 16
        for (int kk = 0; kk < HDIM; kk++) {
            float qv[8], kv[4];
            *(float4*)(qv)     = *(const float4*)&Qs[kk * SQ + ty * 8];
            *(float4*)(qv + 4) = *(const float4*)&Qs[kk * SQ + ty * 8 + 4];
            *(float4*)(kv)     = *(const float4*)&Ks[kk * SK + tx * 4];
#pragma unroll
            for (int i = 0; i < 8; i++)
#pragma unroll
                for (int j = 0; j < 4; j++)
                    sc[i][j] = fmaf(qv[i], kv[j], sc[i][j]);
        }

        // ---- online softmax (reduce over the 16 tx lanes per row) ----------
#pragma unroll
        for (int i = 0; i < 8; i++) {
            float mt = fmaxf(fmaxf(sc[i][0], sc[i][1]), fmaxf(sc[i][2], sc[i][3]));
            mt *= 0.125f;  // fold the 1/sqrt(64) scale into reduced max path
            // reduce max across tx group (lanes differ only in tx: xor 1,2,4,8)
            mt = fmaxf(mt, __shfl_xor_sync(0xffffffffu, mt, 1));
            mt = fmaxf(mt, __shfl_xor_sync(0xffffffffu, mt, 2));
            mt = fmaxf(mt, __shfl_xor_sync(0xffffffffu, mt, 4));
            mt = fmaxf(mt, __shfl_xor_sync(0xffffffffu, mt, 8));
            float m_new = fmaxf(m_r[i], mt);
            float alpha = __expf(m_r[i] - m_new);
            float lt = 0.f;
#pragma unroll
            for (int j = 0; j < 4; j++) {
                float p = __expf(fmaf(sc[i][j], 0.125f, -m_new));
                sc[i][j] = p;
                lt += p;
            }
            lt += __shfl_xor_sync(0xffffffffu, lt, 1);
            lt += __shfl_xor_sync(0xffffffffu, lt, 2);
            lt += __shfl_xor_sync(0xffffffffu, lt, 4);
            lt += __shfl_xor_sync(0xffffffffu, lt, 8);
            l_r[i] = l_r[i] * alpha + lt;
            m_r[i] = m_new;
#pragma unroll
            for (int d = 0; d < 4; d++) acc[i][d] *= alpha;
        }

        // ---- write P transposed: Ps[k][q] ----------------------------------
#pragma unroll
        for (int j = 0; j < 4; j++) {
            float4 p0 = make_float4(sc[0][j], sc[1][j], sc[2][j], sc[3][j]);
            float4 p1 = make_float4(sc[4][j], sc[5][j], sc[6][j], sc[7][j]);
            *(float4*)&Ps[(tx * 4 + j) * SQ + ty * 8]     = p0;
            *(float4*)&Ps[(tx * 4 + j) * SQ + ty * 8 + 4] = p1;
        }
        __syncthreads();

        // ---- PV: acc[8q][4d] += P[q][j] * V[j][d] --------------------------
#pragma unroll 8
        for (int j = 0; j < BKT; j++) {
            float pv[8], vv[4];
            *(float4*)(pv)     = *(const float4*)&Ps[j * SQ + ty * 8];     // broadcast
            *(float4*)(pv + 4) = *(const float4*)&Ps[j * SQ + ty * 8 + 4];
            *(float4*)(vv)     = *(const float4*)&Vs[j * SK + tx * 4];
#pragma unroll
            for (int i = 0; i < 8; i++)
#pragma unroll
                for (int d = 0; d < 4; d++)
                    acc[i][d] = fmaf(pv[i], vv[d], acc[i][d]);
        }
    }

    // ---- epilogue -----------------------------------------------------------
#pragma unroll
    for (int i = 0; i < 8; i++) {
        float inv = 1.f / l_r[i];
        float* op = att + (size_t)(q0 + ty * 8 + i) * DMODEL + h * HDIM + tx * 4;
        float4 v = make_float4(acc[i][0] * inv, acc[i][1] * inv,
                               acc[i][2] * inv, acc[i][3] * inv);
        *(float4*)op = v;
    }
}

// ---------------------------------------------------------------------------
extern "C" void kernel_launch(void* const* d_in, const int* in_sizes, int n_in,
                              void* d_out, int out_size) {
    const float* x     = (const float*)d_in[0];
    const float* sinp  = (const float*)d_in[1];
    const float* cosp  = (const float*)d_in[2];
    const float* Wqkv  = (const float*)d_in[3];
    const float* bqkv  = (const float*)d_in[4];
    const float* Wproj = (const float*)d_in[5];
    const float* bproj = (const float*)d_in[6];
    float* out = (float*)d_out;

    float* qkv = nullptr;
    float* att = nullptr;
    cudaGetSymbolAddress((void**)&qkv, g_qkv);
    cudaGetSymbolAddress((void**)&att, g_att);

    // 1) QKV = x @ Wqkv^T + b  (M=2048, N=3072, K=1024)
    {
        dim3 grid(3072 / 128, SEQ / 128);
        sgemm_nt<<<grid, 256>>>(x, Wqkv, bqkv, qkv, 3072, DMODEL);
    }
    // 2) RoPE on q and k
    rope_kernel<<<(2 * SEQ * NHEAD * 32) / 256, 256>>>(qkv, sinp, cosp);

    // 3) Flash attention: 16 q-tiles x 16 heads
    cudaFuncSetAttribute(flash_attn, cudaFuncAttributeMaxDynamicSharedMemorySize,
                         SMEM_FLASH);
    {
        dim3 grid(SEQ / BQ, NHEAD);
        flash_attn<<<grid, 256, SMEM_FLASH>>>(qkv, att);
    }
    // 4) out = att @ Wproj^T + b  (M=2048, N=1024, K=1024)
    {
        dim3 grid(DMODEL / 128, SEQ / 128);
        sgemm_nt<<<grid, 256>>>(att, Wproj, bproj, out, DMODEL, DMODEL);
    }
}

// round 6
// speedup vs baseline: 3.3060x; 1.3517x over previous
#include <cuda_runtime.h>
#include <cstdint>

#define SEQ    2048
#define DMODEL 1024
#define NHEAD  16
#define HDIM   64
#define QKV_STRIDE (3 * DMODEL)

// Scratch (device-global: no runtime allocation allowed)
__device__ float g_qkv[SEQ * 3 * DMODEL];   // [S, 3*DIM]  q|k|v packed
__device__ float g_att[SEQ * DMODEL];       // attention output [S, DIM]

// ---------------------------------------------------------------------------
// tf32 helpers
// ---------------------------------------------------------------------------
__device__ __forceinline__ uint32_t f2tf32(float x) {
    uint32_t r;
    asm("cvt.rna.tf32.f32 %0, %1;" : "=r"(r) : "f"(x));
    return r;
}

__device__ __forceinline__ void mma_tf32(float* d, const uint32_t* a,
                                         const uint32_t* b) {
    asm("mma.sync.aligned.m16n8k8.row.col.f32.tf32.tf32.f32 "
        "{%0,%1,%2,%3}, {%4,%5,%6,%7}, {%8,%9}, {%0,%1,%2,%3};"
        : "+f"(d[0]), "+f"(d[1]), "+f"(d[2]), "+f"(d[3])
        : "r"(a[0]), "r"(a[1]), "r"(a[2]), "r"(a[3]),
          "r"(b[0]), "r"(b[1]));
}

// ---------------------------------------------------------------------------
// TF32 tensor-core GEMM (NT): C[M,N] = A[M,K] @ B[N,K]^T + bias[N]
// BM=BN=128, BK=16, 256 threads = 8 warps; warp tile 64x32 (4x4 m16n8k8).
// fp32 -> tf32 conversion happens once at the smem staging store.
// smem row stride 20 words => staging float4 stores and fragment LDS reads
// are bank-conflict-free.
// ---------------------------------------------------------------------------
__global__ __launch_bounds__(256)
void tf32_gemm_nt(const float* __restrict__ A, const float* __restrict__ B,
                  const float* __restrict__ bias, float* __restrict__ C,
                  int N, int K) {
    constexpr int BM = 128, BN = 128, BK = 16, LD = 20;
    __shared__ __align__(16) uint32_t As[BM][LD];
    __shared__ __align__(16) uint32_t Bs[BN][LD];

    const int t    = threadIdx.x;
    const int lane = t & 31;
    const int w    = t >> 5;
    const int wm   = w & 1;        // 0..1 -> 64-row band
    const int wn   = w >> 1;       // 0..3 -> 32-col band
    const int g    = lane >> 2;    // group id 0..7
    const int tg   = lane & 3;     // thread-in-group 0..3
    const int bm   = blockIdx.y * BM;
    const int bn   = blockIdx.x * BN;

    // Staging: each thread loads 2 float4 per tensor (rows lr, lr+64; k col lc)
    const int lr = t >> 2;            // 0..63
    const int lc = (t & 3) * 4;       // 0,4,8,12
    const float* Ag = A + (size_t)(bm + lr) * K + lc;
    const float* Bg = B + (size_t)(bn + lr) * K + lc;
    const size_t rowskip = (size_t)64 * K;

    float acc[4][4][4];
#pragma unroll
    for (int mt = 0; mt < 4; mt++)
#pragma unroll
        for (int nt = 0; nt < 4; nt++)
#pragma unroll
            for (int e = 0; e < 4; e++) acc[mt][nt][e] = 0.f;

    float4 pa0 = *(const float4*)(Ag);
    float4 pa1 = *(const float4*)(Ag + rowskip);
    float4 pb0 = *(const float4*)(Bg);
    float4 pb1 = *(const float4*)(Bg + rowskip);

    for (int k0 = 0; k0 < K; k0 += BK) {
        // stage (convert to tf32 bits)
        As[lr][lc + 0] = f2tf32(pa0.x); As[lr][lc + 1] = f2tf32(pa0.y);
        As[lr][lc + 2] = f2tf32(pa0.z); As[lr][lc + 3] = f2tf32(pa0.w);
        As[lr + 64][lc + 0] = f2tf32(pa1.x); As[lr + 64][lc + 1] = f2tf32(pa1.y);
        As[lr + 64][lc + 2] = f2tf32(pa1.z); As[lr + 64][lc + 3] = f2tf32(pa1.w);
        Bs[lr][lc + 0] = f2tf32(pb0.x); Bs[lr][lc + 1] = f2tf32(pb0.y);
        Bs[lr][lc + 2] = f2tf32(pb0.z); Bs[lr][lc + 3] = f2tf32(pb0.w);
        Bs[lr + 64][lc + 0] = f2tf32(pb1.x); Bs[lr + 64][lc + 1] = f2tf32(pb1.y);
        Bs[lr + 64][lc + 2] = f2tf32(pb1.z); Bs[lr + 64][lc + 3] = f2tf32(pb1.w);
        __syncthreads();

        if (k0 + BK < K) {   // prefetch next K-slab while computing this one
            pa0 = *(const float4*)(Ag + k0 + BK);
            pa1 = *(const float4*)(Ag + k0 + BK + rowskip);
            pb0 = *(const float4*)(Bg + k0 + BK);
            pb1 = *(const float4*)(Bg + k0 + BK + rowskip);
        }

#pragma unroll
        for (int ks = 0; ks < BK; ks += 8) {
            uint32_t af[4][4], bf[4][2];
#pragma unroll
            for (int mt = 0; mt < 4; mt++) {
                int row = wm * 64 + mt * 16 + g;
                af[mt][0] = As[row][ks + tg];
                af[mt][1] = As[row + 8][ks + tg];
                af[mt][2] = As[row][ks + tg + 4];
                af[mt][3] = As[row + 8][ks + tg + 4];
            }
#pragma unroll
            for (int nt = 0; nt < 4; nt++) {
                int col = wn * 32 + nt * 8 + g;
                bf[nt][0] = Bs[col][ks + tg];
                bf[nt][1] = Bs[col][ks + tg + 4];
            }
#pragma unroll
            for (int mt = 0; mt < 4; mt++)
#pragma unroll
                for (int nt = 0; nt < 4; nt++)
                    mma_tf32(acc[mt][nt], af[mt], bf[nt]);
        }
        __syncthreads();
    }

    // epilogue: fragment layout c0,c1 @ (g, 2tg..2tg+1), c2,c3 @ (g+8, ...)
#pragma unroll
    for (int nt = 0; nt < 4; nt++) {
        int col = bn + wn * 32 + nt * 8 + tg * 2;
        float b0 = bias[col], b1 = bias[col + 1];
#pragma unroll
        for (int mt = 0; mt < 4; mt++) {
            int row = bm + wm * 64 + mt * 16 + g;
            float2 v0 = make_float2(acc[mt][nt][0] + b0, acc[mt][nt][1] + b1);
            float2 v1 = make_float2(acc[mt][nt][2] + b0, acc[mt][nt][3] + b1);
            *(float2*)(C + (size_t)row * N + col)       = v0;
            *(float2*)(C + (size_t)(row + 8) * N + col) = v1;
        }
    }
}

// ---------------------------------------------------------------------------
// RoPE applied in-place to q and k portions of g_qkv.
// ---------------------------------------------------------------------------
__global__ __launch_bounds__(256)
void rope_kernel(float* __restrict__ qkv, const float* __restrict__ sinp,
                 const float* __restrict__ cosp) {
    int idx = blockIdx.x * blockDim.x + threadIdx.x;
    int d     = idx & 31;
    int h     = (idx >> 5) & (NHEAD - 1);
    int s     = (idx >> 9) & (SEQ - 1);
    int which = idx >> 20;            // 0 = q, 1 = k
    float* base = qkv + (size_t)s * QKV_STRIDE + which * DMODEL + h * HDIM;
    float x1 = base[d];
    float x2 = base[d + 32];
    float cs = cosp[s * HDIM + d];
    float sn = sinp[s * HDIM + d];
    base[d]      = x1 * cs - x2 * sn;
    base[d + 32] = x2 * cs + x1 * sn;
}

// ---------------------------------------------------------------------------
// Flash attention v2 (fp32, online softmax, 2-D register tiling). Unchanged
// from R4 (fastest passing version); tensor-core flash is next round.
// ---------------------------------------------------------------------------
constexpr int BQ  = 128;
constexpr int BKT = 64;
constexpr int SQ  = BQ + 4;
constexpr int SK  = BKT + 4;
constexpr int SMEM_FLASH =
    (HDIM * SQ + HDIM * SK + BKT * SK + BKT * SQ) * (int)sizeof(float); // 100 KB

__global__ __launch_bounds__(256, 2)
void flash_attn(const float* __restrict__ qkv, float* __restrict__ att) {
    extern __shared__ float sm[];
    float* Qs = sm;                     // [HDIM][SQ]   d-major
    float* Ks = Qs + HDIM * SQ;         // [HDIM][SK]   d-major
    float* Vs = Ks + HDIM * SK;         // [BKT][SK]    k-major
    float* Ps = Vs + BKT * SK;          // [BKT][SQ]    k-major (P transposed)

    const int h  = blockIdx.y;
    const int q0 = blockIdx.x * BQ;
    const int t  = threadIdx.x;
    const int tx = t & 15;
    const int ty = t >> 4;

    {
        const float* qg = qkv + h * HDIM;
#pragma unroll
        for (int it = 0; it < 8; it++) {
            int li = it * 256 + t;
            int q  = li >> 4;
            int d4 = li & 15;
            float4 v = *(const float4*)(qg + (size_t)(q0 + q) * QKV_STRIDE + d4 * 4);
            Qs[(d4 * 4 + 0) * SQ + q] = v.x;
            Qs[(d4 * 4 + 1) * SQ + q] = v.y;
            Qs[(d4 * 4 + 2) * SQ + q] = v.z;
            Qs[(d4 * 4 + 3) * SQ + q] = v.w;
        }
    }

    float m_r[8], l_r[8], acc[8][4];
#pragma unroll
    for (int i = 0; i < 8; i++) {
        m_r[i] = -3.0e38f; l_r[i] = 0.f;
#pragma unroll
        for (int d = 0; d < 4; d++) acc[i][d] = 0.f;
    }

    const float* kbase = qkv + DMODEL + h * HDIM;
    const float* vbase = qkv + 2 * DMODEL + h * HDIM;

    for (int kt = 0; kt < SEQ / BKT; kt++) {
        const int kk0 = kt * BKT;
        __syncthreads();
#pragma unroll
        for (int it = 0; it < 4; it++) {
            int li = it * 256 + t;
            int k  = li >> 4;
            int d4 = li & 15;
            float4 kv = *(const float4*)(kbase + (size_t)(kk0 + k) * QKV_STRIDE + d4 * 4);
            float4 vv = *(const float4*)(vbase + (size_t)(kk0 + k) * QKV_STRIDE + d4 * 4);
            Ks[(d4 * 4 + 0) * SK + k] = kv.x;
            Ks[(d4 * 4 + 1) * SK + k] = kv.y;
            Ks[(d4 * 4 + 2) * SK + k] = kv.z;
            Ks[(d4 * 4 + 3) * SK + k] = kv.w;
            *(float4*)&Vs[k * SK + d4 * 4] = vv;
        }
        __syncthreads();

        float sc[8][4];
#pragma unroll
        for (int i = 0; i < 8; i++)
#pragma unroll
            for (int j = 0; j < 4; j++) sc[i][j] = 0.f;

#pragma unroll 16
        for (int kk = 0; kk < HDIM; kk++) {
            float qv[8], kv[4];
            *(float4*)(qv)     = *(const float4*)&Qs[kk * SQ + ty * 8];
            *(float4*)(qv + 4) = *(const float4*)&Qs[kk * SQ + ty * 8 + 4];
            *(float4*)(kv)     = *(const float4*)&Ks[kk * SK + tx * 4];
#pragma unroll
            for (int i = 0; i < 8; i++)
#pragma unroll
                for (int j = 0; j < 4; j++)
                    sc[i][j] = fmaf(qv[i], kv[j], sc[i][j]);
        }

#pragma unroll
        for (int i = 0; i < 8; i++) {
            float mt = fmaxf(fmaxf(sc[i][0], sc[i][1]), fmaxf(sc[i][2], sc[i][3]));
            mt *= 0.125f;
            mt = fmaxf(mt, __shfl_xor_sync(0xffffffffu, mt, 1));
            mt = fmaxf(mt, __shfl_xor_sync(0xffffffffu, mt, 2));
            mt = fmaxf(mt, __shfl_xor_sync(0xffffffffu, mt, 4));
            mt = fmaxf(mt, __shfl_xor_sync(0xffffffffu, mt, 8));
            float m_new = fmaxf(m_r[i], mt);
            float alpha = __expf(m_r[i] - m_new);
            float lt = 0.f;
#pragma unroll
            for (int j = 0; j < 4; j++) {
                float p = __expf(fmaf(sc[i][j], 0.125f, -m_new));
                sc[i][j] = p;
                lt += p;
            }
            lt += __shfl_xor_sync(0xffffffffu, lt, 1);
            lt += __shfl_xor_sync(0xffffffffu, lt, 2);
            lt += __shfl_xor_sync(0xffffffffu, lt, 4);
            lt += __shfl_xor_sync(0xffffffffu, lt, 8);
            l_r[i] = l_r[i] * alpha + lt;
            m_r[i] = m_new;
#pragma unroll
            for (int d = 0; d < 4; d++) acc[i][d] *= alpha;
        }

#pragma unroll
        for (int j = 0; j < 4; j++) {
            float4 p0 = make_float4(sc[0][j], sc[1][j], sc[2][j], sc[3][j]);
            float4 p1 = make_float4(sc[4][j], sc[5][j], sc[6][j], sc[7][j]);
            *(float4*)&Ps[(tx * 4 + j) * SQ + ty * 8]     = p0;
            *(float4*)&Ps[(tx * 4 + j) * SQ + ty * 8 + 4] = p1;
        }
        __syncthreads();

#pragma unroll 8
        for (int j = 0; j < BKT; j++) {
            float pv[8], vv[4];
            *(float4*)(pv)     = *(const float4*)&Ps[j * SQ + ty * 8];
            *(float4*)(pv + 4) = *(const float4*)&Ps[j * SQ + ty * 8 + 4];
            *(float4*)(vv)     = *(const float4*)&Vs[j * SK + tx * 4];
#pragma unroll
            for (int i = 0; i < 8; i++)
#pragma unroll
                for (int d = 0; d < 4; d++)
                    acc[i][d] = fmaf(pv[i], vv[d], acc[i][d]);
        }
    }

#pragma unroll
    for (int i = 0; i < 8; i++) {
        float inv = 1.f / l_r[i];
        float* op = att + (size_t)(q0 + ty * 8 + i) * DMODEL + h * HDIM + tx * 4;
        float4 v = make_float4(acc[i][0] * inv, acc[i][1] * inv,
                               acc[i][2] * inv, acc[i][3] * inv);
        *(float4*)op = v;
    }
}

// ---------------------------------------------------------------------------
extern "C" void kernel_launch(void* const* d_in, const int* in_sizes, int n_in,
                              void* d_out, int out_size) {
    const float* x     = (const float*)d_in[0];
    const float* sinp  = (const float*)d_in[1];
    const float* cosp  = (const float*)d_in[2];
    const float* Wqkv  = (const float*)d_in[3];
    const float* bqkv  = (const float*)d_in[4];
    const float* Wproj = (const float*)d_in[5];
    const float* bproj = (const float*)d_in[6];
    float* out = (float*)d_out;

    float* qkv = nullptr;
    float* att = nullptr;
    cudaGetSymbolAddress((void**)&qkv, g_qkv);
    cudaGetSymbolAddress((void**)&att, g_att);

    // 1) QKV = x @ Wqkv^T + b  (M=2048, N=3072, K=1024) — tf32 tensor cores
    {
        dim3 grid(3072 / 128, SEQ / 128);
        tf32_gemm_nt<<<grid, 256>>>(x, Wqkv, bqkv, qkv, 3072, DMODEL);
    }
    // 2) RoPE on q and k
    rope_kernel<<<(2 * SEQ * NHEAD * 32) / 256, 256>>>(qkv, sinp, cosp);

    // 3) Flash attention: 16 q-tiles x 16 heads (fp32)
    cudaFuncSetAttribute(flash_attn, cudaFuncAttributeMaxDynamicSharedMemorySize,
                         SMEM_FLASH);
    {
        dim3 grid(SEQ / BQ, NHEAD);
        flash_attn<<<grid, 256, SMEM_FLASH>>>(qkv, att);
    }
    // 4) out = att @ Wproj^T + b  (M=2048, N=1024, K=1024) — tf32 tensor cores
    {
        dim3 grid(DMODEL / 128, SEQ / 128);
        tf32_gemm_nt<<<grid, 256>>>(att, Wproj, bproj, out, DMODEL, DMODEL);
    }
}

// round 7
// speedup vs baseline: 4.0564x; 1.2270x over previous
#include <cuda_runtime.h>
#include <cstdint>

#define SEQ    2048
#define DMODEL 1024
#define NHEAD  16
#define HDIM   64
#define QKV_STRIDE (3 * DMODEL)

// Scratch (device-global: no runtime allocation allowed)
__device__ float g_qkv[SEQ * 3 * DMODEL];   // [S, 3*DIM]  q|k|v packed
__device__ float g_att[SEQ * DMODEL];       // attention output [S, DIM]

// ---------------------------------------------------------------------------
// tf32 helpers
// ---------------------------------------------------------------------------
__device__ __forceinline__ uint32_t f2tf32(float x) {
    uint32_t r;
    asm("cvt.rna.tf32.f32 %0, %1;" : "=r"(r) : "f"(x));
    return r;
}

__device__ __forceinline__ void split_tf32(float x, uint32_t& hi, uint32_t& lo) {
    hi = f2tf32(x);
    lo = f2tf32(x - __uint_as_float(hi));
}

__device__ __forceinline__ void mma_tf32(float* d, const uint32_t* a,
                                         const uint32_t* b) {
    asm("mma.sync.aligned.m16n8k8.row.col.f32.tf32.tf32.f32 "
        "{%0,%1,%2,%3}, {%4,%5,%6,%7}, {%8,%9}, {%0,%1,%2,%3};"
        : "+f"(d[0]), "+f"(d[1]), "+f"(d[2]), "+f"(d[3])
        : "r"(a[0]), "r"(a[1]), "r"(a[2]), "r"(a[3]),
          "r"(b[0]), "r"(b[1]));
}

// ---------------------------------------------------------------------------
// TF32 tensor-core GEMM (NT): C[M,N] = A[M,K] @ B[N,K]^T + bias[N]
// (unchanged from R5 — passing at 62us for proj)
// ---------------------------------------------------------------------------
__global__ __launch_bounds__(256)
void tf32_gemm_nt(const float* __restrict__ A, const float* __restrict__ B,
                  const float* __restrict__ bias, float* __restrict__ C,
                  int N, int K) {
    constexpr int BM = 128, BN = 128, BK = 16, LD = 20;
    __shared__ __align__(16) uint32_t As[BM][LD];
    __shared__ __align__(16) uint32_t Bs[BN][LD];

    const int t    = threadIdx.x;
    const int lane = t & 31;
    const int w    = t >> 5;
    const int wm   = w & 1;
    const int wn   = w >> 1;
    const int g    = lane >> 2;
    const int tg   = lane & 3;
    const int bm   = blockIdx.y * BM;
    const int bn   = blockIdx.x * BN;

    const int lr = t >> 2;
    const int lc = (t & 3) * 4;
    const float* Ag = A + (size_t)(bm + lr) * K + lc;
    const float* Bg = B + (size_t)(bn + lr) * K + lc;
    const size_t rowskip = (size_t)64 * K;

    float acc[4][4][4];
#pragma unroll
    for (int mt = 0; mt < 4; mt++)
#pragma unroll
        for (int nt = 0; nt < 4; nt++)
#pragma unroll
            for (int e = 0; e < 4; e++) acc[mt][nt][e] = 0.f;

    float4 pa0 = *(const float4*)(Ag);
    float4 pa1 = *(const float4*)(Ag + rowskip);
    float4 pb0 = *(const float4*)(Bg);
    float4 pb1 = *(const float4*)(Bg + rowskip);

    for (int k0 = 0; k0 < K; k0 += BK) {
        As[lr][lc + 0] = f2tf32(pa0.x); As[lr][lc + 1] = f2tf32(pa0.y);
        As[lr][lc + 2] = f2tf32(pa0.z); As[lr][lc + 3] = f2tf32(pa0.w);
        As[lr + 64][lc + 0] = f2tf32(pa1.x); As[lr + 64][lc + 1] = f2tf32(pa1.y);
        As[lr + 64][lc + 2] = f2tf32(pa1.z); As[lr + 64][lc + 3] = f2tf32(pa1.w);
        Bs[lr][lc + 0] = f2tf32(pb0.x); Bs[lr][lc + 1] = f2tf32(pb0.y);
        Bs[lr][lc + 2] = f2tf32(pb0.z); Bs[lr][lc + 3] = f2tf32(pb0.w);
        Bs[lr + 64][lc + 0] = f2tf32(pb1.x); Bs[lr + 64][lc + 1] = f2tf32(pb1.y);
        Bs[lr + 64][lc + 2] = f2tf32(pb1.z); Bs[lr + 64][lc + 3] = f2tf32(pb1.w);
        __syncthreads();

        if (k0 + BK < K) {
            pa0 = *(const float4*)(Ag + k0 + BK);
            pa1 = *(const float4*)(Ag + k0 + BK + rowskip);
            pb0 = *(const float4*)(Bg + k0 + BK);
            pb1 = *(const float4*)(Bg + k0 + BK + rowskip);
        }

#pragma unroll
        for (int ks = 0; ks < BK; ks += 8) {
            uint32_t af[4][4], bf[4][2];
#pragma unroll
            for (int mt = 0; mt < 4; mt++) {
                int row = wm * 64 + mt * 16 + g;
                af[mt][0] = As[row][ks + tg];
                af[mt][1] = As[row + 8][ks + tg];
                af[mt][2] = As[row][ks + tg + 4];
                af[mt][3] = As[row + 8][ks + tg + 4];
            }
#pragma unroll
            for (int nt = 0; nt < 4; nt++) {
                int col = wn * 32 + nt * 8 + g;
                bf[nt][0] = Bs[col][ks + tg];
                bf[nt][1] = Bs[col][ks + tg + 4];
            }
#pragma unroll
            for (int mt = 0; mt < 4; mt++)
#pragma unroll
                for (int nt = 0; nt < 4; nt++)
                    mma_tf32(acc[mt][nt], af[mt], bf[nt]);
        }
        __syncthreads();
    }

#pragma unroll
    for (int nt = 0; nt < 4; nt++) {
        int col = bn + wn * 32 + nt * 8 + tg * 2;
        float b0 = bias[col], b1 = bias[col + 1];
#pragma unroll
        for (int mt = 0; mt < 4; mt++) {
            int row = bm + wm * 64 + mt * 16 + g;
            float2 v0 = make_float2(acc[mt][nt][0] + b0, acc[mt][nt][1] + b1);
            float2 v1 = make_float2(acc[mt][nt][2] + b0, acc[mt][nt][3] + b1);
            *(float2*)(C + (size_t)row * N + col)       = v0;
            *(float2*)(C + (size_t)(row + 8) * N + col) = v1;
        }
    }
}

// ---------------------------------------------------------------------------
// RoPE applied in-place to q and k portions of g_qkv.
// ---------------------------------------------------------------------------
__global__ __launch_bounds__(256)
void rope_kernel(float* __restrict__ qkv, const float* __restrict__ sinp,
                 const float* __restrict__ cosp) {
    int idx = blockIdx.x * blockDim.x + threadIdx.x;
    int d     = idx & 31;
    int h     = (idx >> 5) & (NHEAD - 1);
    int s     = (idx >> 9) & (SEQ - 1);
    int which = idx >> 20;            // 0 = q, 1 = k
    float* base = qkv + (size_t)s * QKV_STRIDE + which * DMODEL + h * HDIM;
    float x1 = base[d];
    float x2 = base[d + 32];
    float cs = cosp[s * HDIM + d];
    float sn = sinp[s * HDIM + d];
    base[d]      = x1 * cs - x2 * sn;
    base[d + 32] = x2 * cs + x1 * sn;
}

// ---------------------------------------------------------------------------
// Tensor-core flash attention with 3xTF32 error compensation.
// Block = (head, 128 queries), 256 threads = 8 warps, warp owns 16 q rows.
// K-tile = 64 keys. Q fragments (scaled, hi/lo split) persist in registers.
// K/V staged hi/lo in smem; P exchanged via per-warp-private smem region.
// Strides: Ks/Ps = 68 (bank = 4g+tg, injective), Vs = 72 (bank = 8tg+g).
// ---------------------------------------------------------------------------
constexpr int FBQ = 128;
constexpr int FBK = 64;
constexpr int KS_LD = 68;
constexpr int VS_LD = 72;
constexpr int PS_LD = 68;
constexpr int SMEM_FATC =
    (2 * FBK * KS_LD + 2 * FBK * VS_LD + 2 * FBQ * PS_LD) * (int)sizeof(uint32_t);

__global__ __launch_bounds__(256, 1)
void flash_attn_tc(const float* __restrict__ qkv, float* __restrict__ att) {
    extern __shared__ uint32_t su[];
    uint32_t* Ks_hi = su;
    uint32_t* Ks_lo = Ks_hi + FBK * KS_LD;
    uint32_t* Vs_hi = Ks_lo + FBK * KS_LD;
    uint32_t* Vs_lo = Vs_hi + FBK * VS_LD;
    uint32_t* Ps_hi = Vs_lo + FBK * VS_LD;
    uint32_t* Ps_lo = Ps_hi + FBQ * PS_LD;

    const int h  = blockIdx.y;
    const int q0 = blockIdx.x * FBQ;
    const int t  = threadIdx.x;
    const int lane = t & 31;
    const int w  = t >> 5;
    const int g  = lane >> 2;
    const int tg = lane & 3;
    const int r0 = w * 16 + g;       // first m-row this thread touches
    const int r1 = r0 + 8;

    // ---- Q fragments: load once, scale by 1/sqrt(64), split hi/lo ----------
    uint32_t qa_hi[8][4], qa_lo[8][4];
    {
        const float* qg = qkv + (size_t)q0 * QKV_STRIDE + h * HDIM;
        const float* q_r0 = qg + (size_t)r0 * QKV_STRIDE;
        const float* q_r1 = qg + (size_t)r1 * QKV_STRIDE;
#pragma unroll
        for (int kk = 0; kk < 8; kk++) {
            int c0 = kk * 8 + tg, c1 = c0 + 4;
            split_tf32(q_r0[c0] * 0.125f, qa_hi[kk][0], qa_lo[kk][0]);
            split_tf32(q_r1[c0] * 0.125f, qa_hi[kk][1], qa_lo[kk][1]);
            split_tf32(q_r0[c1] * 0.125f, qa_hi[kk][2], qa_lo[kk][2]);
            split_tf32(q_r1[c1] * 0.125f, qa_hi[kk][3], qa_lo[kk][3]);
        }
    }

    float m0 = -1e30f, m1 = -1e30f, l0 = 0.f, l1 = 0.f;
    float oacc[8][4];
#pragma unroll
    for (int nt = 0; nt < 8; nt++)
#pragma unroll
        for (int e = 0; e < 4; e++) oacc[nt][e] = 0.f;

    const float* kg = qkv + DMODEL + h * HDIM;
    const float* vg = qkv + 2 * DMODEL + h * HDIM;

    for (int kt = 0; kt < SEQ / FBK; kt++) {
        __syncthreads();   // previous tile fully consumed
        // ---- stage K,V tile (hi/lo tf32 split at store) --------------------
#pragma unroll
        for (int it = 0; it < 4; it++) {
            int li  = it * 256 + t;          // 1024 float4 per tensor
            int key = li >> 4;
            int d4  = (li & 15) * 4;
            size_t goff = (size_t)(kt * FBK + key) * QKV_STRIDE + d4;
            float4 kv = *(const float4*)(kg + goff);
            float4 vv = *(const float4*)(vg + goff);
            split_tf32(kv.x, Ks_hi[key * KS_LD + d4 + 0], Ks_lo[key * KS_LD + d4 + 0]);
            split_tf32(kv.y, Ks_hi[key * KS_LD + d4 + 1], Ks_lo[key * KS_LD + d4 + 1]);
            split_tf32(kv.z, Ks_hi[key * KS_LD + d4 + 2], Ks_lo[key * KS_LD + d4 + 2]);
            split_tf32(kv.w, Ks_hi[key * KS_LD + d4 + 3], Ks_lo[key * KS_LD + d4 + 3]);
            split_tf32(vv.x, Vs_hi[key * VS_LD + d4 + 0], Vs_lo[key * VS_LD + d4 + 0]);
            split_tf32(vv.y, Vs_hi[key * VS_LD + d4 + 1], Vs_lo[key * VS_LD + d4 + 1]);
            split_tf32(vv.z, Vs_hi[key * VS_LD + d4 + 2], Vs_lo[key * VS_LD + d4 + 2]);
            split_tf32(vv.w, Vs_hi[key * VS_LD + d4 + 3], Vs_lo[key * VS_LD + d4 + 3]);
        }
        __syncthreads();

        // ---- S = (Q*scale) @ K^T  (3xTF32) ---------------------------------
        float sacc[8][4];
#pragma unroll
        for (int nt = 0; nt < 8; nt++)
#pragma unroll
            for (int e = 0; e < 4; e++) sacc[nt][e] = 0.f;

#pragma unroll
        for (int kk = 0; kk < 8; kk++) {
            int kc = kk * 8;
#pragma unroll
            for (int nt = 0; nt < 8; nt++) {
                int krow = nt * 8 + g;
                uint32_t bh[2], bl[2];
                bh[0] = Ks_hi[krow * KS_LD + kc + tg];
                bh[1] = Ks_hi[krow * KS_LD + kc + tg + 4];
                bl[0] = Ks_lo[krow * KS_LD + kc + tg];
                bl[1] = Ks_lo[krow * KS_LD + kc + tg + 4];
                mma_tf32(sacc[nt], qa_hi[kk], bh);
                mma_tf32(sacc[nt], qa_lo[kk], bh);
                mma_tf32(sacc[nt], qa_hi[kk], bl);
            }
        }

        // ---- online softmax -------------------------------------------------
        float mx0 = sacc[0][0], mx1 = sacc[0][2];
#pragma unroll
        for (int nt = 0; nt < 8; nt++) {
            mx0 = fmaxf(mx0, fmaxf(sacc[nt][0], sacc[nt][1]));
            mx1 = fmaxf(mx1, fmaxf(sacc[nt][2], sacc[nt][3]));
        }
        mx0 = fmaxf(mx0, __shfl_xor_sync(0xffffffffu, mx0, 1));
        mx0 = fmaxf(mx0, __shfl_xor_sync(0xffffffffu, mx0, 2));
        mx1 = fmaxf(mx1, __shfl_xor_sync(0xffffffffu, mx1, 1));
        mx1 = fmaxf(mx1, __shfl_xor_sync(0xffffffffu, mx1, 2));

        float nm0 = fmaxf(m0, mx0), nm1 = fmaxf(m1, mx1);
        float a0 = __expf(m0 - nm0), a1 = __expf(m1 - nm1);
        float s0 = 0.f, s1 = 0.f;
#pragma unroll
        for (int nt = 0; nt < 8; nt++) {
            int c = nt * 8 + 2 * tg;
            float p00 = __expf(sacc[nt][0] - nm0);
            float p01 = __expf(sacc[nt][1] - nm0);
            float p10 = __expf(sacc[nt][2] - nm1);
            float p11 = __expf(sacc[nt][3] - nm1);
            s0 += p00 + p01;
            s1 += p10 + p11;
            split_tf32(p00, Ps_hi[r0 * PS_LD + c],     Ps_lo[r0 * PS_LD + c]);
            split_tf32(p01, Ps_hi[r0 * PS_LD + c + 1], Ps_lo[r0 * PS_LD + c + 1]);
            split_tf32(p10, Ps_hi[r1 * PS_LD + c],     Ps_lo[r1 * PS_LD + c]);
            split_tf32(p11, Ps_hi[r1 * PS_LD + c + 1], Ps_lo[r1 * PS_LD + c + 1]);
        }
        s0 += __shfl_xor_sync(0xffffffffu, s0, 1);
        s0 += __shfl_xor_sync(0xffffffffu, s0, 2);
        s1 += __shfl_xor_sync(0xffffffffu, s1, 1);
        s1 += __shfl_xor_sync(0xffffffffu, s1, 2);
        l0 = l0 * a0 + s0;
        l1 = l1 * a1 + s1;
        m0 = nm0; m1 = nm1;
#pragma unroll
        for (int nt = 0; nt < 8; nt++) {
            oacc[nt][0] *= a0; oacc[nt][1] *= a0;
            oacc[nt][2] *= a1; oacc[nt][3] *= a1;
        }
        __syncwarp();   // P region is per-warp-private: warp-level sync suffices

        // ---- O += P @ V  (3xTF32) ------------------------------------------
#pragma unroll
        for (int kk = 0; kk < 8; kk++) {
            int kc = kk * 8;
            uint32_t pah[4], pal[4];
            pah[0] = Ps_hi[r0 * PS_LD + kc + tg];
            pah[1] = Ps_hi[r1 * PS_LD + kc + tg];
            pah[2] = Ps_hi[r0 * PS_LD + kc + tg + 4];
            pah[3] = Ps_hi[r1 * PS_LD + kc + tg + 4];
            pal[0] = Ps_lo[r0 * PS_LD + kc + tg];
            pal[1] = Ps_lo[r1 * PS_LD + kc + tg];
            pal[2] = Ps_lo[r0 * PS_LD + kc + tg + 4];
            pal[3] = Ps_lo[r1 * PS_LD + kc + tg + 4];
#pragma unroll
            for (int nt = 0; nt < 8; nt++) {
                int dcol = nt * 8 + g;
                uint32_t bh[2], bl[2];
                bh[0] = Vs_hi[(kc + tg) * VS_LD + dcol];
                bh[1] = Vs_hi[(kc + tg + 4) * VS_LD + dcol];
                bl[0] = Vs_lo[(kc + tg) * VS_LD + dcol];
                bl[1] = Vs_lo[(kc + tg + 4) * VS_LD + dcol];
                mma_tf32(oacc[nt], pah, bh);
                mma_tf32(oacc[nt], pal, bh);
                mma_tf32(oacc[nt], pah, bl);
            }
        }
    }

    // ---- epilogue -----------------------------------------------------------
    float inv0 = 1.f / l0, inv1 = 1.f / l1;
#pragma unroll
    for (int nt = 0; nt < 8; nt++) {
        int col = h * HDIM + nt * 8 + 2 * tg;
        *(float2*)(att + (size_t)(q0 + r0) * DMODEL + col) =
            make_float2(oacc[nt][0] * inv0, oacc[nt][1] * inv0);
        *(float2*)(att + (size_t)(q0 + r1) * DMODEL + col) =
            make_float2(oacc[nt][2] * inv1, oacc[nt][3] * inv1);
    }
}

// ---------------------------------------------------------------------------
extern "C" void kernel_launch(void* const* d_in, const int* in_sizes, int n_in,
                              void* d_out, int out_size) {
    const float* x     = (const float*)d_in[0];
    const float* sinp  = (const float*)d_in[1];
    const float* cosp  = (const float*)d_in[2];
    const float* Wqkv  = (const float*)d_in[3];
    const float* bqkv  = (const float*)d_in[4];
    const float* Wproj = (const float*)d_in[5];
    const float* bproj = (const float*)d_in[6];
    float* out = (float*)d_out;

    float* qkv = nullptr;
    float* att = nullptr;
    cudaGetSymbolAddress((void**)&qkv, g_qkv);
    cudaGetSymbolAddress((void**)&att, g_att);

    // 1) QKV = x @ Wqkv^T + b  (tf32 tensor cores)
    {
        dim3 grid(3072 / 128, SEQ / 128);
        tf32_gemm_nt<<<grid, 256>>>(x, Wqkv, bqkv, qkv, 3072, DMODEL);
    }
    // 2) RoPE on q and k
    rope_kernel<<<(2 * SEQ * NHEAD * 32) / 256, 256>>>(qkv, sinp, cosp);

    // 3) Flash attention (tensor cores, 3xTF32)
    cudaFuncSetAttribute(flash_attn_tc, cudaFuncAttributeMaxDynamicSharedMemorySize,
                         SMEM_FATC);
    {
        dim3 grid(SEQ / FBQ, NHEAD);
        flash_attn_tc<<<grid, 256, SMEM_FATC>>>(qkv, att);
    }
    // 4) out = att @ Wproj^T + b  (tf32 tensor cores)
    {
        dim3 grid(DMODEL / 128, SEQ / 128);
        tf32_gemm_nt<<<grid, 256>>>(att, Wproj, bproj, out, DMODEL, DMODEL);
    }
}